// round 12
// baseline (speedup 1.0000x reference)
#include <cuda_runtime.h>
#include <cstdint>

#define NNODES 100000
#define NEDGES 640000
#define HID    128

// ---------------- scratch (device globals) ----------------------------------
__device__ float g_Q[(size_t)NNODES * HID];
__device__ float g_K[(size_t)NNODES * HID];
__device__ float g_V[(size_t)NNODES * HID];
__device__ float g_AGG[(size_t)NNODES * HID];
__device__ int   g_deg[NNODES];
__device__ int   g_rowptr[NNODES];
__device__ int   g_cursor[NNODES];
__device__ int   g_perm[NEDGES];     // destination node ids, CSR-grouped
__device__ int   g_total;

// ---------------- helpers ----------------------------------------------------
__device__ __forceinline__ uint32_t f2tf32(float x) {
    uint32_t r;
    asm("cvt.rna.tf32.f32 %0, %1;" : "=r"(r) : "f"(x));
    return r;
}

__device__ __forceinline__ void mma_tf32(float& c0, float& c1, float& c2, float& c3,
                                         uint32_t a0, uint32_t a1, uint32_t a2, uint32_t a3,
                                         uint32_t b0, uint32_t b1) {
    asm volatile(
        "mma.sync.aligned.m16n8k8.row.col.f32.tf32.tf32.f32 "
        "{%0,%1,%2,%3}, {%4,%5,%6,%7}, {%8,%9}, {%0,%1,%2,%3};"
        : "+f"(c0), "+f"(c1), "+f"(c2), "+f"(c3)
        : "r"(a0), "r"(a1), "r"(a2), "r"(a3), "r"(b0), "r"(b1));
}

// ---------------- persistent GEMM: 512 thr, 2 CTAs/SM (8 warps/SMSP) ---------
// Y[M,128] = X[M,128] @ W^T + b.
// W staged tf32(RNA), pair-interleaved (pos(k)=(k&~7)|((k&3)<<1)|((k>>2)&1))
// so a (k,k+4) B pair is one LDS.64. X tile (64 rows) streams raw fp32 via
// cp.async.cg (stride 132 words -> conflict-free LDS.32 A). A feeds mma as
// raw fp32 bits (tf32 truncation — validated rel_err 6.0e-4 < 1e-3).
// 16 warps: warp = 16 rows x 32 cols (mg = w>>2, nq = w&3).
#define SLDW 136
#define SXW  132
#define TROWS 64
#define GEMM_SMEM ((128 * SLDW + TROWS * SXW) * 4)
#define GTH 512

__device__ __forceinline__ void stage_w(uint32_t* sW, const float* __restrict__ W, int tid) {
    #pragma unroll
    for (int j = 0; j < 8; j++) {
        int f = j * GTH + tid;
        int r = f >> 5, c4 = f & 31, c = c4 * 4;
        float4 w4 = *(const float4*)(W + r * HID + c);
        int base = r * SLDW + (c & ~7) + (c4 & 1);
        sW[base + 0] = f2tf32(w4.x);
        sW[base + 2] = f2tf32(w4.y);
        sW[base + 4] = f2tf32(w4.z);
        sW[base + 6] = f2tf32(w4.w);
    }
}

__device__ __forceinline__ void cp_async_tile(float* sX, const float* __restrict__ X,
                                              int tile, int M, int tid) {
    uint32_t sbase = (uint32_t)__cvta_generic_to_shared(sX);
    int rbase = tile * TROWS;
    #pragma unroll
    for (int j = 0; j < 4; j++) {
        int f = j * GTH + tid;
        int r = f >> 5, c4 = f & 31;
        int gr = rbase + r;
        if (gr < M) {
            uint32_t sa = sbase + (uint32_t)(r * SXW + c4 * 4) * 4u;
            asm volatile("cp.async.cg.shared.global [%0], [%1], 16;"
                         :: "r"(sa), "l"(X + (size_t)gr * HID + c4 * 4));
        }
        // OOB rows: stale smem harmless — those output rows are masked.
    }
}

__device__ __forceinline__ void tile_compute(
    const float* __restrict__ sX, const uint32_t* __restrict__ sW,
    const float* __restrict__ b0, float* __restrict__ Y0,
    int tile, int M, int tid) {

    const int w = tid >> 5, lane = tid & 31;
    const int g = lane >> 2, tig = lane & 3;
    const int mg = w >> 2;              // 4 groups of 16 rows
    const int nbase = (w & 3) * 32;     // 4 column quarters

    float c[4][4];
    #pragma unroll
    for (int nt = 0; nt < 4; nt++)
        c[nt][0] = c[nt][1] = c[nt][2] = c[nt][3] = 0.f;

    const uint32_t* ax = (const uint32_t*)(sX + (mg * 16 + g) * SXW) + tig;

    #pragma unroll 4
    for (int kt = 0; kt < 16; kt++) {
        const int ko = kt * 8;
        // rows g, g+8 in the 16-row group; k = ko+tig, ko+tig+4 (raw fp32 bits)
        uint32_t a0  = ax[ko];
        uint32_t a0b = ax[ko + 4];
        uint32_t a1  = ax[ko + 8 * SXW];
        uint32_t a1b = ax[ko + 8 * SXW + 4];
        #pragma unroll
        for (int nt = 0; nt < 4; nt++) {
            const uint32_t* bw = sW + (nbase + nt * 8 + g) * SLDW + ko + tig * 2;
            uint2 b = *(const uint2*)bw;
            mma_tf32(c[nt][0], c[nt][1], c[nt][2], c[nt][3],
                     a0, a1, a0b, a1b, b.x, b.y);
        }
    }

    const int row0 = tile * TROWS + mg * 16 + g;
    const int row1 = row0 + 8;
    #pragma unroll
    for (int nt = 0; nt < 4; nt++) {
        int col = nbase + nt * 8 + tig * 2;
        float bb0 = __ldg(b0 + col), bb1 = __ldg(b0 + col + 1);
        if (row0 < M) *(float2*)(Y0 + (size_t)row0 * HID + col) =
            make_float2(c[nt][0] + bb0, c[nt][1] + bb1);
        if (row1 < M) *(float2*)(Y0 + (size_t)row1 * HID + col) =
            make_float2(c[nt][2] + bb0, c[nt][3] + bb1);
    }
}

extern "C" __global__ void __launch_bounds__(GTH, 2)
gemm_p1(const float* __restrict__ X, const float* __restrict__ W0,
        const float* __restrict__ b0, float* __restrict__ Y0, int M) {
    extern __shared__ uint32_t smem[];
    uint32_t* sW = smem;
    float* sX = (float*)(smem + 128 * SLDW);

    const int tid = threadIdx.x;
    const int ntiles = (M + TROWS - 1) / TROWS;

    stage_w(sW, W0, tid);

    for (int t = blockIdx.x; t < ntiles; t += gridDim.x) {
        cp_async_tile(sX, X, t, M, tid);
        asm volatile("cp.async.commit_group;");
        asm volatile("cp.async.wait_group 0;");
        __syncthreads();                         // tile visible to all warps
        tile_compute(sX, sW, b0, Y0, t, M, tid);
        __syncthreads();                         // done reading before overwrite
    }
}

// ---------------- CSR build --------------------------------------------------
extern "C" __global__ void hist_kernel(const int* __restrict__ s_idx, int E) {
    int e = blockIdx.x * blockDim.x + threadIdx.x;
    if (e == 0) g_total = 0;
    if (e < E) atomicAdd(&g_deg[s_idx[e]], 1);
}

extern "C" __global__ void __launch_bounds__(1024) alloc_kernel(int n) {
    __shared__ int wsum[32];
    __shared__ int sbase;
    const int tid = threadIdx.x, lane = tid & 31, wid = tid >> 5;
    int i = blockIdx.x * 1024 + tid;
    int v = (i < n) ? g_deg[i] : 0;
    int x = v;
    #pragma unroll
    for (int o = 1; o < 32; o <<= 1) {
        int y = __shfl_up_sync(0xffffffffu, x, o);
        if (lane >= o) x += y;
    }
    if (lane == 31) wsum[wid] = x;
    __syncthreads();
    if (wid == 0) {
        int s = wsum[lane];
        #pragma unroll
        for (int o = 1; o < 32; o <<= 1) {
            int y = __shfl_up_sync(0xffffffffu, s, o);
            if (lane >= o) s += y;
        }
        wsum[lane] = s;
    }
    __syncthreads();
    if (tid == 0) sbase = atomicAdd(&g_total, wsum[31]);
    __syncthreads();
    int excl = x - v + (wid > 0 ? wsum[wid - 1] : 0);
    if (i < n) {
        int off = sbase + excl;
        g_rowptr[i] = off;
        g_cursor[i] = off;
    }
}

extern "C" __global__ void scatter_kernel(const int* __restrict__ s_idx,
                                          const int* __restrict__ d_idx, int E) {
    int e = blockIdx.x * blockDim.x + threadIdx.x;
    if (e < E) {
        int pos = atomicAdd(&g_cursor[s_idx[e]], 1);
        g_perm[pos] = d_idx[e];
    }
}

// ---------------- per-node attention (warp per node, CSR, unroll-4) ----------
extern "C" __global__ void __launch_bounds__(256) node_attn_kernel(int n_nodes) {
    int node = (int)((blockIdx.x * 256u + threadIdx.x) >> 5);
    if (node >= n_nodes) return;
    const int lane = threadIdx.x & 31;   // 4 lanes per head (16 floats)

    const int beg = g_rowptr[node];
    const int end = beg + g_deg[node];

    const float4 q4 = __ldcs((const float4*)(g_Q + (size_t)node * HID) + lane);
    float4 acc = make_float4(0.f, 0.f, 0.f, 0.f);
    float z = 0.f;

    for (int i = beg; i < end; i += 4) {
        const int rem = end - i;
        int d0 = __ldg(g_perm + i);
        int d1 = (rem > 1) ? __ldg(g_perm + i + 1) : d0;
        int d2 = (rem > 2) ? __ldg(g_perm + i + 2) : d0;
        int d3 = (rem > 3) ? __ldg(g_perm + i + 3) : d0;

        float4 k0 = __ldg((const float4*)(g_K + (size_t)d0 * HID) + lane);
        float4 v0 = __ldg((const float4*)(g_V + (size_t)d0 * HID) + lane);
        float4 k1 = __ldg((const float4*)(g_K + (size_t)d1 * HID) + lane);
        float4 v1 = __ldg((const float4*)(g_V + (size_t)d1 * HID) + lane);
        float4 k2 = __ldg((const float4*)(g_K + (size_t)d2 * HID) + lane);
        float4 v2 = __ldg((const float4*)(g_V + (size_t)d2 * HID) + lane);
        float4 k3 = __ldg((const float4*)(g_K + (size_t)d3 * HID) + lane);
        float4 v3 = __ldg((const float4*)(g_V + (size_t)d3 * HID) + lane);

        float s0 = q4.x * k0.x + q4.y * k0.y + q4.z * k0.z + q4.w * k0.w;
        float s1 = q4.x * k1.x + q4.y * k1.y + q4.z * k1.z + q4.w * k1.w;
        float s2 = q4.x * k2.x + q4.y * k2.y + q4.z * k2.z + q4.w * k2.w;
        float s3 = q4.x * k3.x + q4.y * k3.y + q4.z * k3.z + q4.w * k3.w;
        s0 += __shfl_xor_sync(0xffffffffu, s0, 1);
        s1 += __shfl_xor_sync(0xffffffffu, s1, 1);
        s2 += __shfl_xor_sync(0xffffffffu, s2, 1);
        s3 += __shfl_xor_sync(0xffffffffu, s3, 1);
        s0 += __shfl_xor_sync(0xffffffffu, s0, 2);
        s1 += __shfl_xor_sync(0xffffffffu, s1, 2);
        s2 += __shfl_xor_sync(0xffffffffu, s2, 2);
        s3 += __shfl_xor_sync(0xffffffffu, s3, 2);

        float p0 = __expf(s0 * 0.25f);                       // 1/sqrt(16)
        float p1 = (rem > 1) ? __expf(s1 * 0.25f) : 0.f;
        float p2 = (rem > 2) ? __expf(s2 * 0.25f) : 0.f;
        float p3 = (rem > 3) ? __expf(s3 * 0.25f) : 0.f;

        z += (p0 + p1) + (p2 + p3);
        acc.x += p0 * v0.x + p1 * v1.x + p2 * v2.x + p3 * v3.x;
        acc.y += p0 * v0.y + p1 * v1.y + p2 * v2.y + p3 * v3.y;
        acc.z += p0 * v0.z + p1 * v1.z + p2 * v2.z + p3 * v3.z;
        acc.w += p0 * v0.w + p1 * v1.w + p2 * v2.w + p3 * v3.w;
    }

    float inv = (z > 0.f) ? (1.f / z) : 0.f;
    __stcs((float4*)(g_AGG + (size_t)node * HID) + lane,
           make_float4(acc.x * inv, acc.y * inv, acc.z * inv, acc.w * inv));
}

// ---------------- launch -----------------------------------------------------
extern "C" void kernel_launch(void* const* d_in, const int* in_sizes, int n_in,
                              void* d_out, int out_size) {
    const float* src_x = (const float*)d_in[0];
    const float* dst_x = (const float*)d_in[1];
    const float* Wq = (const float*)d_in[2];
    const float* bq = (const float*)d_in[3];
    const float* Wk = (const float*)d_in[4];
    const float* bk = (const float*)d_in[5];
    const float* Wv = (const float*)d_in[6];
    const float* bv = (const float*)d_in[7];
    const float* Wo = (const float*)d_in[8];
    const float* bo = (const float*)d_in[9];
    const int* ei = (const int*)d_in[10];

    const int N = in_sizes[0] / HID;
    const int E = in_sizes[10] / 2;
    const int* s_idx = ei;
    const int* d_idx = ei + E;

    float *Qp, *Kp, *Vp, *Ap;
    cudaGetSymbolAddress((void**)&Qp, g_Q);
    cudaGetSymbolAddress((void**)&Kp, g_K);
    cudaGetSymbolAddress((void**)&Vp, g_V);
    cudaGetSymbolAddress((void**)&Ap, g_AGG);
    void* degp;
    cudaGetSymbolAddress(&degp, g_deg);

    int sm_count = 148;
    cudaDeviceGetAttribute(&sm_count, cudaDevAttrMultiProcessorCount, 0);

    cudaFuncSetAttribute(gemm_p1, cudaFuncAttributeMaxDynamicSharedMemorySize, GEMM_SMEM);

    // Lazy one-time stream/event infra (no device memory involved).
    static cudaStream_t s_csr = nullptr;
    static cudaEvent_t ev_fork = nullptr, ev_join = nullptr;
    if (s_csr == nullptr) {
        cudaStreamCreateWithFlags(&s_csr, cudaStreamNonBlocking);
        cudaEventCreateWithFlags(&ev_fork, cudaEventDisableTiming);
        cudaEventCreateWithFlags(&ev_join, cudaEventDisableTiming);
    }

    // Fork: CSR build runs concurrently with the K/V/Q GEMMs.
    cudaEventRecord(ev_fork, 0);
    cudaStreamWaitEvent(s_csr, ev_fork, 0);

    cudaMemsetAsync(degp, 0, (size_t)N * sizeof(int), s_csr);
    hist_kernel<<<(E + 255) / 256, 256, 0, s_csr>>>(s_idx, E);
    alloc_kernel<<<(N + 1023) / 1024, 1024, 0, s_csr>>>(N);
    scatter_kernel<<<(E + 255) / 256, 256, 0, s_csr>>>(s_idx, d_idx, E);
    cudaEventRecord(ev_join, s_csr);

    // Main stream: projections (2 CTAs/SM, 512 threads, 8 warps/SMSP)
    const int ggrid = 2 * sm_count;
    gemm_p1<<<ggrid, GTH, GEMM_SMEM>>>(dst_x, Wk, bk, Kp, N);
    gemm_p1<<<ggrid, GTH, GEMM_SMEM>>>(dst_x, Wv, bv, Vp, N);
    gemm_p1<<<ggrid, GTH, GEMM_SMEM>>>(src_x, Wq, bq, Qp, N);

    // Join: attention needs CSR + Q/K/V.
    cudaStreamWaitEvent(0, ev_join, 0);
    node_attn_kernel<<<(N + 7) / 8, 256>>>(N);

    // output projection
    gemm_p1<<<ggrid, GTH, GEMM_SMEM>>>(Ap, Wo, bo, (float*)d_out, N);
}

// round 13
// speedup vs baseline: 1.0605x; 1.0605x over previous
#include <cuda_runtime.h>
#include <cuda_fp16.h>
#include <cstdint>

#define NNODES 100000
#define NEDGES 640000
#define HID    128

// ---------------- scratch (device globals) ----------------------------------
__device__ float g_Q[(size_t)NNODES * HID];
__device__ float g_KV[(size_t)NNODES * 2 * HID];   // per node: K[128] then V[128]
__device__ float g_AGG[(size_t)NNODES * HID];
__device__ int   g_deg[NNODES];
__device__ int   g_rowptr[NNODES];
__device__ int   g_cursor[NNODES];
__device__ int   g_perm[NEDGES];     // destination node ids, CSR-grouped
__device__ int   g_total;

// ---------------- helpers ----------------------------------------------------
__device__ __forceinline__ uint32_t packh2(float lo, float hi) {
    __half2 h = __floats2half2_rn(lo, hi);     // .x = lo (even k), .y = hi
    return *reinterpret_cast<uint32_t*>(&h);
}

__device__ __forceinline__ void mma_f16(float& c0, float& c1, float& c2, float& c3,
                                        uint32_t a0, uint32_t a1, uint32_t a2, uint32_t a3,
                                        uint32_t b0, uint32_t b1) {
    asm volatile(
        "mma.sync.aligned.m16n8k16.row.col.f32.f16.f16.f32 "
        "{%0,%1,%2,%3}, {%4,%5,%6,%7}, {%8,%9}, {%0,%1,%2,%3};"
        : "+f"(c0), "+f"(c1), "+f"(c2), "+f"(c3)
        : "r"(a0), "r"(a1), "r"(a2), "r"(a3), "r"(b0), "r"(b1));
}

// ---------------- persistent fp16-mma GEMM, double-buffered, 2 CTAs/SM -------
// Y[M,128] = X[M,128] @ W^T + b   (Y row stride RS: 128 normal, 256 for K/V).
// W staged fp16 (RNE), k-pair words, pair-interleaved within each 8-word kt
// window: pos(k2)=(k2&~7)|((k2&3)<<1)|((k2>>2)&1) so the (k2, k2+4) B-fragment
// pair is one LDS.64. Row stride 68 words -> B bank = 4g+2tig (2-way max).
// X tiles stream raw fp32 via cp.async.cg double buffer (stride 132 words);
// A fragments: LDS.64 float2 (adjacent k) -> one cvt.f16x2 pack each.
#define SWW  68     // W row stride (u32 words of fp16x2)
#define SXW  132
#define TROWS 64
#define GEMM_SMEM ((128 * SWW + 2 * TROWS * SXW) * 4)   // 100 KB

__device__ __forceinline__ int wpos(int k2) {
    return (k2 & ~7) | ((k2 & 3) << 1) | ((k2 >> 2) & 1);
}

__device__ __forceinline__ void stage_w(uint32_t* sW, const float* __restrict__ W, int tid) {
    #pragma unroll
    for (int j = 0; j < 16; j++) {
        int f = j * 256 + tid;
        int r = f >> 5, c4 = f & 31;
        float4 w4 = *(const float4*)(W + r * HID + c4 * 4);
        sW[r * SWW + wpos(2 * c4)]     = packh2(w4.x, w4.y);
        sW[r * SWW + wpos(2 * c4 + 1)] = packh2(w4.z, w4.w);
    }
}

__device__ __forceinline__ void cp_async_tile(float* sX, const float* __restrict__ X,
                                              int tile, int M, int tid) {
    uint32_t sbase = (uint32_t)__cvta_generic_to_shared(sX);
    int rbase = tile * TROWS;
    #pragma unroll
    for (int j = 0; j < 8; j++) {
        int f = j * 256 + tid;
        int r = f >> 5, c4 = f & 31;
        int gr = rbase + r;
        if (gr < M) {
            uint32_t sa = sbase + (uint32_t)(r * SXW + c4 * 4) * 4u;
            asm volatile("cp.async.cg.shared.global [%0], [%1], 16;"
                         :: "r"(sa), "l"(X + (size_t)gr * HID + c4 * 4));
        }
        // OOB rows: stale smem harmless — those output rows are masked.
    }
}

__device__ __forceinline__ void tile_compute(
    const float* __restrict__ sX, const uint32_t* __restrict__ sW,
    const float* __restrict__ b0, float* __restrict__ Y0,
    int tile, int M, int RS, int tid) {

    const int w = tid >> 5, lane = tid & 31;
    const int g = lane >> 2, tig = lane & 3;
    const int mg = w >> 2;              // 2 groups of 32 rows
    const int nbase = (w & 3) * 32;     // 4 column quarters

    float c[2][4][4];
    #pragma unroll
    for (int s = 0; s < 2; s++)
        #pragma unroll
        for (int nt = 0; nt < 4; nt++)
            c[s][nt][0] = c[s][nt][1] = c[s][nt][2] = c[s][nt][3] = 0.f;

    const int R = mg * 32;

    #pragma unroll
    for (int kt = 0; kt < 8; kt++) {
        const int ko = kt * 16;
        // A fragments, tile0 rows R+g / R+g+8, tile1 rows R+g+16 / R+g+24.
        float2 f00 = *(const float2*)(sX + (R + g)      * SXW + ko + 2 * tig);
        float2 f01 = *(const float2*)(sX + (R + g + 8)  * SXW + ko + 2 * tig);
        float2 f02 = *(const float2*)(sX + (R + g)      * SXW + ko + 2 * tig + 8);
        float2 f03 = *(const float2*)(sX + (R + g + 8)  * SXW + ko + 2 * tig + 8);
        float2 f10 = *(const float2*)(sX + (R + g + 16) * SXW + ko + 2 * tig);
        float2 f11 = *(const float2*)(sX + (R + g + 24) * SXW + ko + 2 * tig);
        float2 f12 = *(const float2*)(sX + (R + g + 16) * SXW + ko + 2 * tig + 8);
        float2 f13 = *(const float2*)(sX + (R + g + 24) * SXW + ko + 2 * tig + 8);
        uint32_t A0 = packh2(f00.x, f00.y), A1 = packh2(f01.x, f01.y);
        uint32_t A2 = packh2(f02.x, f02.y), A3 = packh2(f03.x, f03.y);
        uint32_t A4 = packh2(f10.x, f10.y), A5 = packh2(f11.x, f11.y);
        uint32_t A6 = packh2(f12.x, f12.y), A7 = packh2(f13.x, f13.y);
        #pragma unroll
        for (int nt = 0; nt < 4; nt++) {
            uint2 b = *(const uint2*)(sW + (nbase + nt * 8 + g) * SWW + kt * 8 + 2 * tig);
            mma_f16(c[0][nt][0], c[0][nt][1], c[0][nt][2], c[0][nt][3],
                    A0, A1, A2, A3, b.x, b.y);
            mma_f16(c[1][nt][0], c[1][nt][1], c[1][nt][2], c[1][nt][3],
                    A4, A5, A6, A7, b.x, b.y);
        }
    }

    #pragma unroll
    for (int s = 0; s < 2; s++) {
        const int row0 = tile * TROWS + mg * 32 + s * 16 + g;
        const int row1 = row0 + 8;
        #pragma unroll
        for (int nt = 0; nt < 4; nt++) {
            int col = nbase + nt * 8 + tig * 2;
            float bb0 = __ldg(b0 + col), bb1 = __ldg(b0 + col + 1);
            if (row0 < M) *(float2*)(Y0 + (size_t)row0 * RS + col) =
                make_float2(c[s][nt][0] + bb0, c[s][nt][1] + bb1);
            if (row1 < M) *(float2*)(Y0 + (size_t)row1 * RS + col) =
                make_float2(c[s][nt][2] + bb0, c[s][nt][3] + bb1);
        }
    }
}

extern "C" __global__ void __launch_bounds__(256, 2)
gemm_h(const float* __restrict__ X, const float* __restrict__ W0,
       const float* __restrict__ b0, float* __restrict__ Y0, int M, int RS) {
    extern __shared__ uint32_t smem[];
    uint32_t* sW = smem;
    float* sXa = (float*)(smem + 128 * SWW);
    float* sXb = sXa + TROWS * SXW;

    const int tid = threadIdx.x;
    const int ntiles = (M + TROWS - 1) / TROWS;

    stage_w(sW, W0, tid);

    int t = blockIdx.x;
    if (t >= ntiles) return;

    cp_async_tile(sXa, X, t, M, tid);
    asm volatile("cp.async.commit_group;");

    int p = 0;
    for (; t < ntiles; t += gridDim.x) {
        int tn = t + gridDim.x;
        float* cur = p ? sXb : sXa;
        float* nxt = p ? sXa : sXb;
        if (tn < ntiles) {
            cp_async_tile(nxt, X, tn, M, tid);   // overlaps compute below
            asm volatile("cp.async.commit_group;");
            asm volatile("cp.async.wait_group 1;");
        } else {
            asm volatile("cp.async.wait_group 0;");
        }
        __syncthreads();                          // cur tile visible
        tile_compute(cur, sW, b0, Y0, t, M, RS, tid);
        __syncthreads();                          // done reading cur
        p ^= 1;
    }
}

// ---------------- CSR build --------------------------------------------------
extern "C" __global__ void hist_kernel(const int* __restrict__ s_idx, int E) {
    int e = blockIdx.x * blockDim.x + threadIdx.x;
    if (e == 0) g_total = 0;
    if (e < E) atomicAdd(&g_deg[s_idx[e]], 1);
}

extern "C" __global__ void __launch_bounds__(1024) alloc_kernel(int n) {
    __shared__ int wsum[32];
    __shared__ int sbase;
    const int tid = threadIdx.x, lane = tid & 31, wid = tid >> 5;
    int i = blockIdx.x * 1024 + tid;
    int v = (i < n) ? g_deg[i] : 0;
    int x = v;
    #pragma unroll
    for (int o = 1; o < 32; o <<= 1) {
        int y = __shfl_up_sync(0xffffffffu, x, o);
        if (lane >= o) x += y;
    }
    if (lane == 31) wsum[wid] = x;
    __syncthreads();
    if (wid == 0) {
        int s = wsum[lane];
        #pragma unroll
        for (int o = 1; o < 32; o <<= 1) {
            int y = __shfl_up_sync(0xffffffffu, s, o);
            if (lane >= o) s += y;
        }
        wsum[lane] = s;
    }
    __syncthreads();
    if (tid == 0) sbase = atomicAdd(&g_total, wsum[31]);
    __syncthreads();
    int excl = x - v + (wid > 0 ? wsum[wid - 1] : 0);
    if (i < n) {
        int off = sbase + excl;
        g_rowptr[i] = off;
        g_cursor[i] = off;
    }
}

extern "C" __global__ void scatter_kernel(const int* __restrict__ s_idx,
                                          const int* __restrict__ d_idx, int E) {
    int e = blockIdx.x * blockDim.x + threadIdx.x;
    if (e < E) {
        int pos = atomicAdd(&g_cursor[s_idx[e]], 1);
        g_perm[pos] = d_idx[e];
    }
}

// ---------------- per-node attention (warp per node, CSR, unroll-4) ----------
// K and V for a node are contiguous (1KB) in g_KV -> better gather locality.
extern "C" __global__ void __launch_bounds__(256) node_attn_kernel(int n_nodes) {
    int node = (int)((blockIdx.x * 256u + threadIdx.x) >> 5);
    if (node >= n_nodes) return;
    const int lane = threadIdx.x & 31;   // 4 lanes per head (16 floats)

    const int beg = g_rowptr[node];
    const int end = beg + g_deg[node];

    const float4 q4 = __ldcs((const float4*)(g_Q + (size_t)node * HID) + lane);
    float4 acc = make_float4(0.f, 0.f, 0.f, 0.f);
    float z = 0.f;

    for (int i = beg; i < end; i += 4) {
        const int rem = end - i;
        int d0 = __ldg(g_perm + i);
        int d1 = (rem > 1) ? __ldg(g_perm + i + 1) : d0;
        int d2 = (rem > 2) ? __ldg(g_perm + i + 2) : d0;
        int d3 = (rem > 3) ? __ldg(g_perm + i + 3) : d0;

        const float* p0 = g_KV + (size_t)d0 * 2 * HID;
        const float* p1 = g_KV + (size_t)d1 * 2 * HID;
        const float* p2 = g_KV + (size_t)d2 * 2 * HID;
        const float* p3 = g_KV + (size_t)d3 * 2 * HID;

        float4 k0 = __ldg((const float4*)p0 + lane);
        float4 v0 = __ldg((const float4*)(p0 + HID) + lane);
        float4 k1 = __ldg((const float4*)p1 + lane);
        float4 v1 = __ldg((const float4*)(p1 + HID) + lane);
        float4 k2 = __ldg((const float4*)p2 + lane);
        float4 v2 = __ldg((const float4*)(p2 + HID) + lane);
        float4 k3 = __ldg((const float4*)p3 + lane);
        float4 v3 = __ldg((const float4*)(p3 + HID) + lane);

        float s0 = q4.x * k0.x + q4.y * k0.y + q4.z * k0.z + q4.w * k0.w;
        float s1 = q4.x * k1.x + q4.y * k1.y + q4.z * k1.z + q4.w * k1.w;
        float s2 = q4.x * k2.x + q4.y * k2.y + q4.z * k2.z + q4.w * k2.w;
        float s3 = q4.x * k3.x + q4.y * k3.y + q4.z * k3.z + q4.w * k3.w;
        s0 += __shfl_xor_sync(0xffffffffu, s0, 1);
        s1 += __shfl_xor_sync(0xffffffffu, s1, 1);
        s2 += __shfl_xor_sync(0xffffffffu, s2, 1);
        s3 += __shfl_xor_sync(0xffffffffu, s3, 1);
        s0 += __shfl_xor_sync(0xffffffffu, s0, 2);
        s1 += __shfl_xor_sync(0xffffffffu, s1, 2);
        s2 += __shfl_xor_sync(0xffffffffu, s2, 2);
        s3 += __shfl_xor_sync(0xffffffffu, s3, 2);

        float p0e = __expf(s0 * 0.25f);                      // 1/sqrt(16)
        float p1e = (rem > 1) ? __expf(s1 * 0.25f) : 0.f;
        float p2e = (rem > 2) ? __expf(s2 * 0.25f) : 0.f;
        float p3e = (rem > 3) ? __expf(s3 * 0.25f) : 0.f;

        z += (p0e + p1e) + (p2e + p3e);
        acc.x += p0e * v0.x + p1e * v1.x + p2e * v2.x + p3e * v3.x;
        acc.y += p0e * v0.y + p1e * v1.y + p2e * v2.y + p3e * v3.y;
        acc.z += p0e * v0.z + p1e * v1.z + p2e * v2.z + p3e * v3.z;
        acc.w += p0e * v0.w + p1e * v1.w + p2e * v2.w + p3e * v3.w;
    }

    float inv = (z > 0.f) ? (1.f / z) : 0.f;
    __stcs((float4*)(g_AGG + (size_t)node * HID) + lane,
           make_float4(acc.x * inv, acc.y * inv, acc.z * inv, acc.w * inv));
}

// ---------------- launch -----------------------------------------------------
extern "C" void kernel_launch(void* const* d_in, const int* in_sizes, int n_in,
                              void* d_out, int out_size) {
    const float* src_x = (const float*)d_in[0];
    const float* dst_x = (const float*)d_in[1];
    const float* Wq = (const float*)d_in[2];
    const float* bq = (const float*)d_in[3];
    const float* Wk = (const float*)d_in[4];
    const float* bk = (const float*)d_in[5];
    const float* Wv = (const float*)d_in[6];
    const float* bv = (const float*)d_in[7];
    const float* Wo = (const float*)d_in[8];
    const float* bo = (const float*)d_in[9];
    const int* ei = (const int*)d_in[10];

    const int N = in_sizes[0] / HID;
    const int E = in_sizes[10] / 2;
    const int* s_idx = ei;
    const int* d_idx = ei + E;

    float *Qp, *KVp, *Ap;
    cudaGetSymbolAddress((void**)&Qp, g_Q);
    cudaGetSymbolAddress((void**)&KVp, g_KV);
    cudaGetSymbolAddress((void**)&Ap, g_AGG);
    void* degp;
    cudaGetSymbolAddress(&degp, g_deg);

    int sm_count = 148;
    cudaDeviceGetAttribute(&sm_count, cudaDevAttrMultiProcessorCount, 0);

    cudaFuncSetAttribute(gemm_h, cudaFuncAttributeMaxDynamicSharedMemorySize, GEMM_SMEM);

    // Lazy one-time stream/event infra (no device memory involved).
    static cudaStream_t s_csr = nullptr;
    static cudaEvent_t ev_fork = nullptr, ev_join = nullptr;
    if (s_csr == nullptr) {
        cudaStreamCreateWithFlags(&s_csr, cudaStreamNonBlocking);
        cudaEventCreateWithFlags(&ev_fork, cudaEventDisableTiming);
        cudaEventCreateWithFlags(&ev_join, cudaEventDisableTiming);
    }

    // Fork: CSR build overlaps the K/V/Q GEMMs.
    cudaEventRecord(ev_fork, 0);
    cudaStreamWaitEvent(s_csr, ev_fork, 0);
    cudaMemsetAsync(degp, 0, (size_t)N * sizeof(int), s_csr);
    hist_kernel<<<(E + 255) / 256, 256, 0, s_csr>>>(s_idx, E);
    alloc_kernel<<<(N + 1023) / 1024, 1024, 0, s_csr>>>(N);
    scatter_kernel<<<(E + 255) / 256, 256, 0, s_csr>>>(s_idx, d_idx, E);
    cudaEventRecord(ev_join, s_csr);

    // Projections: K,V into interleaved g_KV (stride 256), Q normal.
    const int ggrid = 2 * sm_count;
    gemm_h<<<ggrid, 256, GEMM_SMEM>>>(dst_x, Wk, bk, KVp,       N, 2 * HID);
    gemm_h<<<ggrid, 256, GEMM_SMEM>>>(dst_x, Wv, bv, KVp + HID, N, 2 * HID);
    gemm_h<<<ggrid, 256, GEMM_SMEM>>>(src_x, Wq, bq, Qp,        N, HID);

    // Join: attention needs CSR + Q/K/V.
    cudaStreamWaitEvent(0, ev_join, 0);
    node_attn_kernel<<<(N + 7) / 8, 256>>>(N);

    // output projection
    gemm_h<<<ggrid, 256, GEMM_SMEM>>>(Ap, Wo, bo, (float*)d_out, N, HID);
}

// round 17
// speedup vs baseline: 1.3597x; 1.2820x over previous
#include <cuda_runtime.h>
#include <cuda_fp16.h>
#include <cstdint>

#define NNODES 100000
#define NEDGES 640000
#define HID    128

// ---------------- scratch (device globals) ----------------------------------
__device__ float    g_Q[(size_t)NNODES * HID];
__device__ uint32_t g_KVh[(size_t)NNODES * 128];   // per node: 64 words K(h2), 64 words V(h2)
__device__ float    g_AGG[(size_t)NNODES * HID];
__device__ int      g_deg[NNODES];
__device__ int      g_rowptr[NNODES];
__device__ int      g_cursor[NNODES];
__device__ int      g_perm[NEDGES];   // destination node ids, CSR-grouped
__device__ int      g_total;

// ---------------- helpers ----------------------------------------------------
__device__ __forceinline__ uint32_t packh2(float lo, float hi) {
    __half2 h = __floats2half2_rn(lo, hi);
    return *reinterpret_cast<uint32_t*>(&h);
}

__device__ __forceinline__ void mma_f16(float& c0, float& c1, float& c2, float& c3,
                                        uint32_t a0, uint32_t a1, uint32_t a2, uint32_t a3,
                                        uint32_t b0, uint32_t b1) {
    asm volatile(
        "mma.sync.aligned.m16n8k16.row.col.f32.f16.f16.f32 "
        "{%0,%1,%2,%3}, {%4,%5,%6,%7}, {%8,%9}, {%0,%1,%2,%3};"
        : "+f"(c0), "+f"(c1), "+f"(c2), "+f"(c3)
        : "r"(a0), "r"(a1), "r"(a2), "r"(a3), "r"(b0), "r"(b1));
}

// ---------------- fp16-mma GEMM framework ------------------------------------
// Y[M,128] = X[M,128] @ W^T + b. W staged fp16(RNE), pair-interleaved
// (pos(k2)=(k2&~7)|((k2&3)<<1)|((k2>>2)&1)), row stride 68 words.
// X tiles stream raw fp32 via cp.async.cg; A packs half2 at fragment load.
// Warp tile 32x32; 8 warps cover 64x128; 2 CTAs/SM overlap staging/compute.
#define SWW  68
#define SXW  132
#define TROWS 64
#define GEMM1_SMEM ((128 * SWW + 2 * TROWS * SXW) * 4)   // Q/O: double-buffered X
#define GEMM2_SMEM ((256 * SWW + TROWS * SXW) * 4)       // KV: 2 W mats, single X

__device__ __forceinline__ int wpos(int k2) {
    return (k2 & ~7) | ((k2 & 3) << 1) | ((k2 >> 2) & 1);
}

__device__ __forceinline__ void stage_w(uint32_t* sW, const float* __restrict__ W, int tid) {
    #pragma unroll
    for (int j = 0; j < 16; j++) {
        int f = j * 256 + tid;
        int r = f >> 5, c4 = f & 31;
        float4 w4 = *(const float4*)(W + r * HID + c4 * 4);
        sW[r * SWW + wpos(2 * c4)]     = packh2(w4.x, w4.y);
        sW[r * SWW + wpos(2 * c4 + 1)] = packh2(w4.z, w4.w);
    }
}

__device__ __forceinline__ void cp_async_tile(float* sX, const float* __restrict__ X,
                                              int tile, int M, int tid) {
    uint32_t sbase = (uint32_t)__cvta_generic_to_shared(sX);
    int rbase = tile * TROWS;
    #pragma unroll
    for (int j = 0; j < 8; j++) {
        int f = j * 256 + tid;
        int r = f >> 5, c4 = f & 31;
        int gr = rbase + r;
        if (gr < M) {
            uint32_t sa = sbase + (uint32_t)(r * SXW + c4 * 4) * 4u;
            asm volatile("cp.async.cg.shared.global [%0], [%1], 16;"
                         :: "r"(sa), "l"(X + (size_t)gr * HID + c4 * 4));
        }
        // OOB rows: stale smem harmless — those output rows are masked.
    }
}

// Load + pack this warp's 8 A fragments for k-tile kt.
__device__ __forceinline__ void lda_pack(uint32_t A[8], const float* __restrict__ sX,
                                         int R, int g, int tig, int kt) {
    const int ko = kt * 16;
    float2 f0 = *(const float2*)(sX + (R + g)      * SXW + ko + 2 * tig);
    float2 f1 = *(const float2*)(sX + (R + g + 8)  * SXW + ko + 2 * tig);
    float2 f2 = *(const float2*)(sX + (R + g)      * SXW + ko + 2 * tig + 8);
    float2 f3 = *(const float2*)(sX + (R + g + 8)  * SXW + ko + 2 * tig + 8);
    float2 f4 = *(const float2*)(sX + (R + g + 16) * SXW + ko + 2 * tig);
    float2 f5 = *(const float2*)(sX + (R + g + 24) * SXW + ko + 2 * tig);
    float2 f6 = *(const float2*)(sX + (R + g + 16) * SXW + ko + 2 * tig + 8);
    float2 f7 = *(const float2*)(sX + (R + g + 24) * SXW + ko + 2 * tig + 8);
    A[0] = packh2(f0.x, f0.y); A[1] = packh2(f1.x, f1.y);
    A[2] = packh2(f2.x, f2.y); A[3] = packh2(f3.x, f3.y);
    A[4] = packh2(f4.x, f4.y); A[5] = packh2(f5.x, f5.y);
    A[6] = packh2(f6.x, f6.y); A[7] = packh2(f7.x, f7.y);
}

// ---------------- gemm_h: fp32 out (Q and O projections) ---------------------
extern "C" __global__ void __launch_bounds__(256, 2)
gemm_h(const float* __restrict__ X, const float* __restrict__ W0,
       const float* __restrict__ b0, float* __restrict__ Y0, int M) {
    extern __shared__ uint32_t smem[];
    uint32_t* sW = smem;
    float* sXa = (float*)(smem + 128 * SWW);
    float* sXb = sXa + TROWS * SXW;

    const int tid = threadIdx.x;
    const int ntiles = (M + TROWS - 1) / TROWS;

    stage_w(sW, W0, tid);

    int t = blockIdx.x;
    if (t >= ntiles) return;

    cp_async_tile(sXa, X, t, M, tid);
    asm volatile("cp.async.commit_group;");

    const int w = tid >> 5, lane = tid & 31;
    const int g = lane >> 2, tig = lane & 3;
    const int mg = w >> 2, nbase = (w & 3) * 32;
    const int R = mg * 32;

    int p = 0;
    for (; t < ntiles; t += gridDim.x) {
        int tn = t + gridDim.x;
        float* cur = p ? sXb : sXa;
        float* nxt = p ? sXa : sXb;
        if (tn < ntiles) {
            cp_async_tile(nxt, X, tn, M, tid);
            asm volatile("cp.async.commit_group;");
            asm volatile("cp.async.wait_group 1;");
        } else {
            asm volatile("cp.async.wait_group 0;");
        }
        __syncthreads();

        float c[2][4][4];
        #pragma unroll
        for (int s = 0; s < 2; s++)
            #pragma unroll
            for (int nt = 0; nt < 4; nt++)
                c[s][nt][0] = c[s][nt][1] = c[s][nt][2] = c[s][nt][3] = 0.f;

        #pragma unroll
        for (int kt = 0; kt < 8; kt++) {
            uint32_t A[8];
            lda_pack(A, cur, R, g, tig, kt);
            #pragma unroll
            for (int nt = 0; nt < 4; nt++) {
                uint2 b = *(const uint2*)(sW + (nbase + nt * 8 + g) * SWW + kt * 8 + 2 * tig);
                mma_f16(c[0][nt][0], c[0][nt][1], c[0][nt][2], c[0][nt][3],
                        A[0], A[1], A[2], A[3], b.x, b.y);
                mma_f16(c[1][nt][0], c[1][nt][1], c[1][nt][2], c[1][nt][3],
                        A[4], A[5], A[6], A[7], b.x, b.y);
            }
        }

        #pragma unroll
        for (int s = 0; s < 2; s++) {
            const int row0 = t * TROWS + mg * 32 + s * 16 + g;
            const int row1 = row0 + 8;
            #pragma unroll
            for (int nt = 0; nt < 4; nt++) {
                int col = nbase + nt * 8 + tig * 2;
                float bb0 = __ldg(b0 + col), bb1 = __ldg(b0 + col + 1);
                if (row0 < M) *(float2*)(Y0 + (size_t)row0 * HID + col) =
                    make_float2(c[s][nt][0] + bb0, c[s][nt][1] + bb1);
                if (row1 < M) *(float2*)(Y0 + (size_t)row1 * HID + col) =
                    make_float2(c[s][nt][2] + bb0, c[s][nt][3] + bb1);
            }
        }
        __syncthreads();
        p ^= 1;
    }
}

// ---------------- gemm_kv: fused K+V, fp16 packed out ------------------------
extern "C" __global__ void __launch_bounds__(256, 2)
gemm_kv(const float* __restrict__ X,
        const float* __restrict__ Wk, const float* __restrict__ bk,
        const float* __restrict__ Wv, const float* __restrict__ bv, int M) {
    extern __shared__ uint32_t smem[];
    uint32_t* sWk = smem;
    uint32_t* sWv = smem + 128 * SWW;
    float* sX = (float*)(smem + 256 * SWW);

    const int tid = threadIdx.x;
    const int ntiles = (M + TROWS - 1) / TROWS;

    stage_w(sWk, Wk, tid);
    stage_w(sWv, Wv, tid);

    const int w = tid >> 5, lane = tid & 31;
    const int g = lane >> 2, tig = lane & 3;
    const int mg = w >> 2, nbase = (w & 3) * 32;
    const int R = mg * 32;

    for (int t = blockIdx.x; t < ntiles; t += gridDim.x) {
        cp_async_tile(sX, X, t, M, tid);
        asm volatile("cp.async.commit_group;");
        asm volatile("cp.async.wait_group 0;");
        __syncthreads();

        float ck[2][4][4], cv[2][4][4];
        #pragma unroll
        for (int s = 0; s < 2; s++)
            #pragma unroll
            for (int nt = 0; nt < 4; nt++) {
                ck[s][nt][0] = ck[s][nt][1] = ck[s][nt][2] = ck[s][nt][3] = 0.f;
                cv[s][nt][0] = cv[s][nt][1] = cv[s][nt][2] = cv[s][nt][3] = 0.f;
            }

        #pragma unroll
        for (int kt = 0; kt < 8; kt++) {
            uint32_t A[8];
            lda_pack(A, sX, R, g, tig, kt);
            #pragma unroll
            for (int nt = 0; nt < 4; nt++) {
                int woff = (nbase + nt * 8 + g) * SWW + kt * 8 + 2 * tig;
                uint2 b1 = *(const uint2*)(sWk + woff);
                mma_f16(ck[0][nt][0], ck[0][nt][1], ck[0][nt][2], ck[0][nt][3],
                        A[0], A[1], A[2], A[3], b1.x, b1.y);
                mma_f16(ck[1][nt][0], ck[1][nt][1], ck[1][nt][2], ck[1][nt][3],
                        A[4], A[5], A[6], A[7], b1.x, b1.y);
                uint2 b2 = *(const uint2*)(sWv + woff);
                mma_f16(cv[0][nt][0], cv[0][nt][1], cv[0][nt][2], cv[0][nt][3],
                        A[0], A[1], A[2], A[3], b2.x, b2.y);
                mma_f16(cv[1][nt][0], cv[1][nt][1], cv[1][nt][2], cv[1][nt][3],
                        A[4], A[5], A[6], A[7], b2.x, b2.y);
            }
        }

        #pragma unroll
        for (int s = 0; s < 2; s++) {
            const int row0 = t * TROWS + mg * 32 + s * 16 + g;
            const int row1 = row0 + 8;
            #pragma unroll
            for (int nt = 0; nt < 4; nt++) {
                int col = nbase + nt * 8 + tig * 2;
                float k0 = __ldg(bk + col), k1 = __ldg(bk + col + 1);
                float v0 = __ldg(bv + col), v1 = __ldg(bv + col + 1);
                if (row0 < M) {
                    g_KVh[(size_t)row0 * 128 + (col >> 1)] =
                        packh2(ck[s][nt][0] + k0, ck[s][nt][1] + k1);
                    g_KVh[(size_t)row0 * 128 + 64 + (col >> 1)] =
                        packh2(cv[s][nt][0] + v0, cv[s][nt][1] + v1);
                }
                if (row1 < M) {
                    g_KVh[(size_t)row1 * 128 + (col >> 1)] =
                        packh2(ck[s][nt][2] + k0, ck[s][nt][3] + k1);
                    g_KVh[(size_t)row1 * 128 + 64 + (col >> 1)] =
                        packh2(cv[s][nt][2] + v0, cv[s][nt][3] + v1);
                }
            }
        }
        __syncthreads();
    }
}

// ---------------- CSR build --------------------------------------------------
extern "C" __global__ void hist_kernel(const int* __restrict__ s_idx, int E) {
    int e = blockIdx.x * blockDim.x + threadIdx.x;
    if (e == 0) g_total = 0;
    if (e < E) atomicAdd(&g_deg[s_idx[e]], 1);
}

extern "C" __global__ void __launch_bounds__(1024) alloc_kernel(int n) {
    __shared__ int wsum[32];
    __shared__ int sbase;
    const int tid = threadIdx.x, lane = tid & 31, wid = tid >> 5;
    int i = blockIdx.x * 1024 + tid;
    int v = (i < n) ? g_deg[i] : 0;
    int x = v;
    #pragma unroll
    for (int o = 1; o < 32; o <<= 1) {
        int y = __shfl_up_sync(0xffffffffu, x, o);
        if (lane >= o) x += y;
    }
    if (lane == 31) wsum[wid] = x;
    __syncthreads();
    if (wid == 0) {
        int s = wsum[lane];
        #pragma unroll
        for (int o = 1; o < 32; o <<= 1) {
            int y = __shfl_up_sync(0xffffffffu, s, o);
            if (lane >= o) s += y;
        }
        wsum[lane] = s;
    }
    __syncthreads();
    if (tid == 0) sbase = atomicAdd(&g_total, wsum[31]);
    __syncthreads();
    int excl = x - v + (wid > 0 ? wsum[wid - 1] : 0);
    if (i < n) {
        int off = sbase + excl;
        g_rowptr[i] = off;
        g_cursor[i] = off;
    }
}

extern "C" __global__ void scatter_kernel(const int* __restrict__ s_idx,
                                          const int* __restrict__ d_idx, int E) {
    int e = blockIdx.x * blockDim.x + threadIdx.x;
    if (e < E) {
        int pos = atomicAdd(&g_cursor[s_idx[e]], 1);
        g_perm[pos] = d_idx[e];
    }
}

// ---------------- per-node attention (warp per node, fp16 KV gather) ---------
// Per edge: one 512B record (K 256B, V 256B) of half2 words; lane owns 4
// values of each (uint2 = 4 halves). fp32 math after conversion.
extern "C" __global__ void __launch_bounds__(256) node_attn_kernel(int n_nodes) {
    int node = (int)((blockIdx.x * 256u + threadIdx.x) >> 5);
    if (node >= n_nodes) return;
    const int lane = threadIdx.x & 31;   // 4 lanes per head (16 values)

    const int beg = g_rowptr[node];
    const int end = beg + g_deg[node];

    const float4 q4 = __ldcs((const float4*)(g_Q + (size_t)node * HID) + lane);
    float4 acc = make_float4(0.f, 0.f, 0.f, 0.f);
    float z = 0.f;

    for (int i = beg; i < end; i += 4) {
        const int rem = end - i;
        int d0 = __ldg(g_perm + i);
        int d1 = (rem > 1) ? __ldg(g_perm + i + 1) : d0;
        int d2 = (rem > 2) ? __ldg(g_perm + i + 2) : d0;
        int d3 = (rem > 3) ? __ldg(g_perm + i + 3) : d0;

        const uint32_t* b0 = g_KVh + (size_t)d0 * 128;
        const uint32_t* b1 = g_KVh + (size_t)d1 * 128;
        const uint32_t* b2 = g_KVh + (size_t)d2 * 128;
        const uint32_t* b3 = g_KVh + (size_t)d3 * 128;

        uint2 kw0 = __ldg((const uint2*)b0 + lane);
        uint2 vw0 = __ldg((const uint2*)(b0 + 64) + lane);
        uint2 kw1 = __ldg((const uint2*)b1 + lane);
        uint2 vw1 = __ldg((const uint2*)(b1 + 64) + lane);
        uint2 kw2 = __ldg((const uint2*)b2 + lane);
        uint2 vw2 = __ldg((const uint2*)(b2 + 64) + lane);
        uint2 kw3 = __ldg((const uint2*)b3 + lane);
        uint2 vw3 = __ldg((const uint2*)(b3 + 64) + lane);

        float2 k0a = __half22float2(*(__half2*)&kw0.x);
        float2 k0b = __half22float2(*(__half2*)&kw0.y);
        float2 k1a = __half22float2(*(__half2*)&kw1.x);
        float2 k1b = __half22float2(*(__half2*)&kw1.y);
        float2 k2a = __half22float2(*(__half2*)&kw2.x);
        float2 k2b = __half22float2(*(__half2*)&kw2.y);
        float2 k3a = __half22float2(*(__half2*)&kw3.x);
        float2 k3b = __half22float2(*(__half2*)&kw3.y);

        float s0 = q4.x * k0a.x + q4.y * k0a.y + q4.z * k0b.x + q4.w * k0b.y;
        float s1 = q4.x * k1a.x + q4.y * k1a.y + q4.z * k1b.x + q4.w * k1b.y;
        float s2 = q4.x * k2a.x + q4.y * k2a.y + q4.z * k2b.x + q4.w * k2b.y;
        float s3 = q4.x * k3a.x + q4.y * k3a.y + q4.z * k3b.x + q4.w * k3b.y;
        s0 += __shfl_xor_sync(0xffffffffu, s0, 1);
        s1 += __shfl_xor_sync(0xffffffffu, s1, 1);
        s2 += __shfl_xor_sync(0xffffffffu, s2, 1);
        s3 += __shfl_xor_sync(0xffffffffu, s3, 1);
        s0 += __shfl_xor_sync(0xffffffffu, s0, 2);
        s1 += __shfl_xor_sync(0xffffffffu, s1, 2);
        s2 += __shfl_xor_sync(0xffffffffu, s2, 2);
        s3 += __shfl_xor_sync(0xffffffffu, s3, 2);

        float p0 = __expf(s0 * 0.25f);                       // 1/sqrt(16)
        float p1 = (rem > 1) ? __expf(s1 * 0.25f) : 0.f;
        float p2 = (rem > 2) ? __expf(s2 * 0.25f) : 0.f;
        float p3 = (rem > 3) ? __expf(s3 * 0.25f) : 0.f;
        z += (p0 + p1) + (p2 + p3);

        float2 v0a = __half22float2(*(__half2*)&vw0.x);
        float2 v0b = __half22float2(*(__half2*)&vw0.y);
        float2 v1a = __half22float2(*(__half2*)&vw1.x);
        float2 v1b = __half22float2(*(__half2*)&vw1.y);
        float2 v2a = __half22float2(*(__half2*)&vw2.x);
        float2 v2b = __half22float2(*(__half2*)&vw2.y);
        float2 v3a = __half22float2(*(__half2*)&vw3.x);
        float2 v3b = __half22float2(*(__half2*)&vw3.y);

        acc.x += p0 * v0a.x + p1 * v1a.x + p2 * v2a.x + p3 * v3a.x;
        acc.y += p0 * v0a.y + p1 * v1a.y + p2 * v2a.y + p3 * v3a.y;
        acc.z += p0 * v0b.x + p1 * v1b.x + p2 * v2b.x + p3 * v3b.x;
        acc.w += p0 * v0b.y + p1 * v1b.y + p2 * v2b.y + p3 * v3b.y;
    }

    float inv = (z > 0.f) ? (1.f / z) : 0.f;
    __stcs((float4*)(g_AGG + (size_t)node * HID) + lane,
           make_float4(acc.x * inv, acc.y * inv, acc.z * inv, acc.w * inv));
}

// ---------------- launch (single stream, no fork — de-risked) ----------------
extern "C" void kernel_launch(void* const* d_in, const int* in_sizes, int n_in,
                              void* d_out, int out_size) {
    const float* src_x = (const float*)d_in[0];
    const float* dst_x = (const float*)d_in[1];
    const float* Wq = (const float*)d_in[2];
    const float* bq = (const float*)d_in[3];
    const float* Wk = (const float*)d_in[4];
    const float* bk = (const float*)d_in[5];
    const float* Wv = (const float*)d_in[6];
    const float* bv = (const float*)d_in[7];
    const float* Wo = (const float*)d_in[8];
    const float* bo = (const float*)d_in[9];
    const int* ei = (const int*)d_in[10];

    const int N = in_sizes[0] / HID;
    const int E = in_sizes[10] / 2;
    const int* s_idx = ei;
    const int* d_idx = ei + E;

    float *Qp, *Ap;
    cudaGetSymbolAddress((void**)&Qp, g_Q);
    cudaGetSymbolAddress((void**)&Ap, g_AGG);
    void* degp;
    cudaGetSymbolAddress(&degp, g_deg);

    int sm_count = 148;
    cudaDeviceGetAttribute(&sm_count, cudaDevAttrMultiProcessorCount, 0);

    cudaFuncSetAttribute(gemm_h,  cudaFuncAttributeMaxDynamicSharedMemorySize, GEMM1_SMEM);
    cudaFuncSetAttribute(gemm_kv, cudaFuncAttributeMaxDynamicSharedMemorySize, GEMM2_SMEM);

    // CSR build (default stream, serialized)
    cudaMemsetAsync(degp, 0, (size_t)N * sizeof(int));
    hist_kernel<<<(E + 255) / 256, 256>>>(s_idx, E);
    alloc_kernel<<<(N + 1023) / 1024, 1024>>>(N);
    scatter_kernel<<<(E + 255) / 256, 256>>>(s_idx, d_idx, E);

    // Projections
    const int ggrid = 2 * sm_count;
    gemm_kv<<<ggrid, 256, GEMM2_SMEM>>>(dst_x, Wk, bk, Wv, bv, N);
    gemm_h<<<ggrid, 256, GEMM1_SMEM>>>(src_x, Wq, bq, Qp, N);

    // fused score/softmax/aggregate
    node_attn_kernel<<<(N + 7) / 8, 256>>>(N);

    // output projection
    gemm_h<<<ggrid, 256, GEMM1_SMEM>>>(Ap, Wo, bo, (float*)d_out, N);
}